// round 4
// baseline (speedup 1.0000x reference)
#include <cuda_runtime.h>
#include <math.h>
#include <stdint.h>

// Problem dims
#define BATCH 32
#define EPS   1e-12f

// ---------------- packed global weight layout (per net, 42240 floats) -------
//  w1 : [tap(5)][o(64)][i(64)]   20480   @ 0
//  w2 : [tap(5)][o(64)][i(64)]   20480   @ 20480
//  w0 : [tap(4)][o(64)][i(4)]     1024   @ 40960
//  wo : [o(64)][ch(4)]             256   @ 41984
#define NET_STRIDE 42240
#define WP_TOTAL   (2 * NET_STRIDE)

__device__ float g_wp[WP_TOTAL];

// ---------------- shared memory layout (floats) -----------------------------
#define SM_W0    0        // 1024
#define SM_WO    1024     // 256
#define SM_H0    1280     // 4096  [64px][64]
#define SM_H1    5376     // 4096
#define SM_Y     9472     // 256   [64px][4ch]
#define SM_X     9728     // 256
#define SM_LS    9984     // 256
#define SM_B0    10240    // 64
#define SM_B1    10304    // 64
#define SM_B2    10368    // 64
#define SM_BO    10432    // 4
#define SM_MLV   10436    // 32   [buf 2][a 4][ch 4] (peer's values land here)
#define SM_WPART 10468    // 256  [warp 16][a 4][ch 4]
#define SM_MBAR  10724    // 2    (8B aligned: 10724*4 = 42896; 42896%8==0)
#define SMEM_FLOATS 10728
#define SMEM_BYTES  (SMEM_FLOATS * 4)

// Mask-A taps (dr,dc): (-1,-1),(-1,0),(-1,1),(0,-1) ; Mask-B: A + (0,0)
__global__ void repack_kernel(const float* __restrict__ mw0, const float* __restrict__ mw1,
                              const float* __restrict__ mw2, const float* __restrict__ mwo,
                              const float* __restrict__ lw0, const float* __restrict__ lw1,
                              const float* __restrict__ lw2, const float* __restrict__ lwo)
{
    int t = blockIdx.x * blockDim.x + threadIdx.x;
    if (t >= WP_TOTAL) return;
    const int krA[4] = {0,0,0,1}, kcA[4] = {0,1,2,0};
    const int krB[5] = {0,0,0,1,1}, kcB[5] = {0,1,2,0,1};
    int net = t / NET_STRIDE;
    int u   = t % NET_STRIDE;
    float v;
    if (u < 20480) {                       // w1: [tap][o][64]
        int tap = u / 4096, rem = u % 4096;
        int o = rem >> 6, i = rem & 63;
        const float* w = net ? lw1 : mw1;
        v = w[((o * 64 + i) * 3 + krB[tap]) * 3 + kcB[tap]];
    } else if (u < 40960) {                // w2
        int u2 = u - 20480;
        int tap = u2 / 4096, rem = u2 % 4096;
        int o = rem >> 6, i = rem & 63;
        const float* w = net ? lw2 : mw2;
        v = w[((o * 64 + i) * 3 + krB[tap]) * 3 + kcB[tap]];
    } else if (u < 41984) {                // w0: [tap][o][4]
        int u2 = u - 40960;
        int tap = u2 / 256, rem = u2 % 256;
        int o = rem >> 2, i = rem & 3;
        const float* w = net ? lw0 : mw0;
        v = w[((o * 4 + i) * 3 + krA[tap]) * 3 + kcA[tap]];
    } else {                               // wo: [o][4]
        int u2 = u - 41984;
        int o = u2 >> 2, ch = u2 & 3;
        const float* w = net ? lwo : mwo;
        v = w[ch * 64 + o];
    }
    g_wp[t] = v;
}

__device__ __forceinline__ float elu1(float v) {
    return v > 0.f ? v : (__expf(v) - 1.f);
}

__device__ __forceinline__ uint32_t smem_u32(const void* p) {
    uint32_t a;
    asm("{ .reg .u64 t; cvta.to.shared.u64 t, %1; cvt.u32.u64 %0, t; }" : "=r"(a) : "l"(p));
    return a;
}

__device__ __forceinline__ void st_remote_f32(uint32_t saddr, uint32_t rank, float v) {
    uint32_t raddr;
    asm volatile("mapa.shared::cluster.u32 %0, %1, %2;" : "=r"(raddr) : "r"(saddr), "r"(rank));
    asm volatile("st.shared::cluster.f32 [%0], %1;" :: "r"(raddr), "f"(v) : "memory");
}

__device__ __forceinline__ void arrive_remote(uint32_t mbar_saddr, uint32_t rank) {
    asm volatile(
        "{\n\t"
        ".reg .b32 r;\n\t"
        "mapa.shared::cluster.u32 r, %0, %1;\n\t"
        "mbarrier.arrive.release.cluster.shared::cluster.b64 _, [r];\n\t"
        "}"
        :: "r"(mbar_saddr), "r"(rank) : "memory");
}

__device__ __forceinline__ void mbar_wait(uint32_t mbar_saddr, uint32_t parity) {
    asm volatile(
        "{\n\t"
        ".reg .pred P1;\n\t"
        "WAIT_LOOP_%=:\n\t"
        "mbarrier.try_wait.parity.acquire.cluster.shared::cta.b64 P1, [%0], %1, 0x989680;\n\t"
        "@P1 bra.uni WAIT_DONE_%=;\n\t"
        "bra.uni WAIT_LOOP_%=;\n\t"
        "WAIT_DONE_%=:\n\t"
        "}"
        :: "r"(mbar_saddr), "r"(parity) : "memory");
}

__device__ __forceinline__ void ffma2(unsigned long long& acc, unsigned long long w,
                                      unsigned long long h) {
    asm("fma.rn.f32x2 %0, %1, %2, %0;" : "+l"(acc) : "l"(w), "l"(h));
}

__device__ __forceinline__ float f2sum(unsigned long long v) {
    return __uint_as_float((uint32_t)v) + __uint_as_float((uint32_t)(v >> 32));
}

__global__ void __cluster_dims__(2, 1, 1) __launch_bounds__(512, 1)
made_kernel(const float* __restrict__ x,
            const float* __restrict__ mb0, const float* __restrict__ mb1,
            const float* __restrict__ mb2, const float* __restrict__ mbo,
            const float* __restrict__ lb0, const float* __restrict__ lb1,
            const float* __restrict__ lb2, const float* __restrict__ lbo,
            float* __restrict__ out)
{
    extern __shared__ float sm[];
    const int tid = threadIdx.x;
    const int b = blockIdx.x >> 1;
    uint32_t net;
    asm("mov.u32 %0, %%cluster_ctarank;" : "=r"(net));
    const uint32_t peer = net ^ 1u;
    const uint32_t smbase = smem_u32(sm);
    const uint32_t mbar = smbase + SM_MBAR * 4u;

    const int o    = tid >> 3;       // 0..63
    const int iq   = tid & 7;        // 0..7 : 8-float i-chunk
    const int lane = tid & 31;
    const int wrp  = tid >> 5;       // 0..15

    // ---- load my weights into registers (coalesced LDG, one-time) ----
    unsigned long long w1r[5][4], w2r[5][4];
    {
        const float* gw = g_wp + net * NET_STRIDE;
        #pragma unroll
        for (int tap = 0; tap < 5; tap++) {
            const ulonglong2* p1 = (const ulonglong2*)(gw + (tap * 64 + o) * 64 + iq * 8);
            ulonglong2 a = p1[0], bq = p1[1];
            w1r[tap][0] = a.x; w1r[tap][1] = a.y; w1r[tap][2] = bq.x; w1r[tap][3] = bq.y;
            const ulonglong2* p2 = (const ulonglong2*)(gw + 20480 + (tap * 64 + o) * 64 + iq * 8);
            ulonglong2 c = p2[0], d = p2[1];
            w2r[tap][0] = c.x; w2r[tap][1] = c.y; w2r[tap][2] = d.x; w2r[tap][3] = d.y;
        }
    }

    // ---- startup: small tables into smem ----
    {
        const float* gw = g_wp + net * NET_STRIDE;
        if (tid < 256) {
            sm[SM_W0 + tid] = gw[40960 + tid];
            sm[SM_W0 + 256 + tid] = gw[40960 + 256 + tid];
            sm[SM_W0 + 512 + tid] = gw[40960 + 512 + tid];
            sm[SM_W0 + 768 + tid] = gw[40960 + 768 + tid];
            sm[SM_WO + tid] = gw[41984 + tid];
            int ch = tid >> 6, p = tid & 63;
            sm[SM_X + p * 4 + ch] = x[b * 256 + tid];
            sm[SM_Y + tid] = 0.f;
        }
        if (tid < 64) {
            sm[SM_B0 + tid] = net ? lb0[tid] : mb0[tid];
            sm[SM_B1 + tid] = net ? lb1[tid] : mb1[tid];
            sm[SM_B2 + tid] = net ? lb2[tid] : mb2[tid];
        }
        if (tid < 4) sm[SM_BO + tid] = net ? lbo[tid] : mbo[tid];
        if (tid == 0)
            asm volatile("mbarrier.init.shared.b64 [%0], %1;" :: "r"(mbar), "r"(16) : "memory");
    }
    __syncthreads();
    asm volatile("barrier.cluster.arrive.aligned;" ::: "memory");
    asm volatile("barrier.cluster.wait.aligned;" ::: "memory");

    const int dRA[4] = {-1,-1,-1, 0}, dCA[4] = {-1, 0, 1,-1};
    const int dRB[5] = {-1,-1,-1, 0, 0}, dCB[5] = {-1, 0, 1,-1, 0};

    for (int s = 0; s < 22; s++) {
        int rlo = (s - 6) > 0 ? (s - 6) / 2 : 0;
        int rhi = (s >> 1) < 7 ? (s >> 1) : 7;
        int npix = rhi - rlo + 1;

        int ra[4], ca[4], pa[4];
        #pragma unroll
        for (int a = 0; a < 4; a++) {
            ra[a] = rlo + a;
            ca[a] = s - 2 * ra[a];
            pa[a] = ra[a] * 8 + ca[a];
        }

        // ---------- layer 0 (mask A, 4 -> 64): threads (o0, a0), tid<256 ----------
        if (tid < 256) {
            int o0 = tid & 63, a0 = tid >> 6;
            if (a0 < npix) {
                float acc = sm[SM_B0 + o0];
                #pragma unroll
                for (int tap = 0; tap < 4; tap++) {
                    int rr = ra[a0] + dRA[tap], cc = ca[a0] + dCA[tap];
                    if (rr >= 0 && cc >= 0 && cc < 8) {
                        float4 w = *(const float4*)(sm + SM_W0 + (tap * 64 + o0) * 4);
                        float4 y4 = *(const float4*)(sm + SM_Y + (rr * 8 + cc) * 4);
                        acc += w.x * y4.x + w.y * y4.y + w.z * y4.z + w.w * y4.w;
                    }
                }
                sm[SM_H0 + pa[a0] * 64 + o0] = elu1(acc);
            }
        }
        __syncthreads();

        // ---------- layer 1 GEMM fused with i-reduction ----------
        {
            unsigned long long acc[4] = {0ull, 0ull, 0ull, 0ull};
            #pragma unroll
            for (int tap = 0; tap < 5; tap++) {
                #pragma unroll
                for (int a = 0; a < 4; a++) {
                    int rr = ra[a] + dRB[tap], cc = ca[a] + dCB[tap];
                    if (a < npix && rr >= 0 && cc >= 0 && cc < 8) {
                        const ulonglong2* hp =
                            (const ulonglong2*)(sm + SM_H0 + (rr * 8 + cc) * 64 + iq * 8);
                        ulonglong2 hA = hp[0], hB = hp[1];
                        ffma2(acc[a], w1r[tap][0], hA.x);
                        ffma2(acc[a], w1r[tap][1], hA.y);
                        ffma2(acc[a], w1r[tap][2], hB.x);
                        ffma2(acc[a], w1r[tap][3], hB.y);
                    }
                }
            }
            float bias = sm[SM_B1 + o];
            #pragma unroll
            for (int a = 0; a < 4; a++) {
                if (a < npix) {
                    float sa = f2sum(acc[a]);
                    sa += __shfl_down_sync(0xffffffffu, sa, 4, 8);
                    sa += __shfl_down_sync(0xffffffffu, sa, 2, 8);
                    sa += __shfl_down_sync(0xffffffffu, sa, 1, 8);
                    if (iq == 0)
                        sm[SM_H1 + pa[a] * 64 + o] = elu1(sa + bias);
                }
            }
        }
        __syncthreads();

        // ---------- layer 2 GEMM fused + 1x1 output conv partials ----------
        {
            unsigned long long acc[4] = {0ull, 0ull, 0ull, 0ull};
            #pragma unroll
            for (int tap = 0; tap < 5; tap++) {
                #pragma unroll
                for (int a = 0; a < 4; a++) {
                    int rr = ra[a] + dRB[tap], cc = ca[a] + dCB[tap];
                    if (a < npix && rr >= 0 && cc >= 0 && cc < 8) {
                        const ulonglong2* hp =
                            (const ulonglong2*)(sm + SM_H1 + (rr * 8 + cc) * 64 + iq * 8);
                        ulonglong2 hA = hp[0], hB = hp[1];
                        ffma2(acc[a], w2r[tap][0], hA.x);
                        ffma2(acc[a], w2r[tap][1], hA.y);
                        ffma2(acc[a], w2r[tap][2], hB.x);
                        ffma2(acc[a], w2r[tap][3], hB.y);
                    }
                }
            }
            float bias = sm[SM_B2 + o];
            float4 wo4 = *(const float4*)(sm + SM_WO + o * 4);
            #pragma unroll
            for (int a = 0; a < 4; a++) {
                if (a < npix) {
                    float sa = f2sum(acc[a]);
                    sa += __shfl_down_sync(0xffffffffu, sa, 4, 8);
                    sa += __shfl_down_sync(0xffffffffu, sa, 2, 8);
                    sa += __shfl_down_sync(0xffffffffu, sa, 1, 8);
                    float v = elu1(sa + bias);   // valid at iq==0 lanes
                    float c0 = v * wo4.x, c1 = v * wo4.y, c2 = v * wo4.z, c3 = v * wo4.w;
                    // reduce over the warp's 4 o's (lanes 0,8,16,24 hold data)
                    c0 += __shfl_down_sync(0xffffffffu, c0, 16);
                    c1 += __shfl_down_sync(0xffffffffu, c1, 16);
                    c2 += __shfl_down_sync(0xffffffffu, c2, 16);
                    c3 += __shfl_down_sync(0xffffffffu, c3, 16);
                    c0 += __shfl_down_sync(0xffffffffu, c0, 8);
                    c1 += __shfl_down_sync(0xffffffffu, c1, 8);
                    c2 += __shfl_down_sync(0xffffffffu, c2, 8);
                    c3 += __shfl_down_sync(0xffffffffu, c3, 8);
                    if (lane == 0) {
                        float* pp = sm + SM_WPART + (wrp * 4 + a) * 4;
                        pp[0] = c0; pp[1] = c1; pp[2] = c2; pp[3] = c3;
                    }
                }
            }
        }
        __syncthreads();

        // ---------- finalize + peer exchange + y update (tid < 16) ----------
        int buf = s & 1;
        if (tid < 16) {
            int a = tid >> 2, ch = tid & 3;
            float v = 0.f;
            if (a < npix) {
                v = sm[SM_BO + ch];
                #pragma unroll
                for (int w = 0; w < 16; w++)
                    v += sm[SM_WPART + (w * 4 + a) * 4 + ch];
                uint32_t off = (uint32_t)(SM_MLV + buf * 16 + a * 4 + ch) * 4u;
                st_remote_f32(smbase + off, peer, v);
            }
            arrive_remote(mbar, peer);
            mbar_wait(mbar, (uint32_t)(s & 1));
            if (a < npix) {
                float pv = sm[SM_MLV + buf * 16 + a * 4 + ch];
                float mu = net ? pv : v;
                float ls = 0.5f * (net ? v : pv);
                int p = pa[a];
                float yv = (sm[SM_X + p * 4 + ch] - mu) / (__expf(ls) + EPS);
                sm[SM_Y + p * 4 + ch] = yv;
                sm[SM_LS + p * 4 + ch] = ls;
            }
        }
        __syncthreads();
    }

    // ---- outputs ----
    if (net == 0) {
        if (tid < 256)
            out[b * 256 + tid] = sm[SM_Y + (tid & 63) * 4 + (tid >> 6)];
    } else {
        if (tid < 32) {
            float a = 0.f;
            #pragma unroll
            for (int k = 0; k < 8; k++) a += sm[SM_LS + tid * 8 + k];
            #pragma unroll
            for (int off = 16; off >= 1; off >>= 1)
                a += __shfl_down_sync(0xffffffffu, a, off);
            if (tid == 0) out[BATCH * 256 + b] = a;
        }
    }

    asm volatile("barrier.cluster.arrive.aligned;" ::: "memory");
    asm volatile("barrier.cluster.wait.aligned;" ::: "memory");
}

extern "C" void kernel_launch(void* const* d_in, const int* in_sizes, int n_in,
                              void* d_out, int out_size)
{
    (void)in_sizes; (void)n_in; (void)out_size;
    const float* x   = (const float*)d_in[0];
    const float* mw0 = (const float*)d_in[1];
    const float* mb0 = (const float*)d_in[2];
    const float* mw1 = (const float*)d_in[3];
    const float* mb1 = (const float*)d_in[4];
    const float* mw2 = (const float*)d_in[5];
    const float* mb2 = (const float*)d_in[6];
    const float* mwo = (const float*)d_in[7];
    const float* mbo = (const float*)d_in[8];
    const float* lw0 = (const float*)d_in[9];
    const float* lb0 = (const float*)d_in[10];
    const float* lw1 = (const float*)d_in[11];
    const float* lb1 = (const float*)d_in[12];
    const float* lw2 = (const float*)d_in[13];
    const float* lb2 = (const float*)d_in[14];
    const float* lwo = (const float*)d_in[15];
    const float* lbo = (const float*)d_in[16];
    float* out = (float*)d_out;

    cudaFuncSetAttribute(made_kernel, cudaFuncAttributeMaxDynamicSharedMemorySize, SMEM_BYTES);

    repack_kernel<<<(WP_TOTAL + 255) / 256, 256>>>(mw0, mw1, mw2, mwo, lw0, lw1, lw2, lwo);
    made_kernel<<<2 * BATCH, 512, SMEM_BYTES>>>(x, mb0, mb1, mb2, mbo,
                                                lb0, lb1, lb2, lbo, out);
}

// round 5
// speedup vs baseline: 1.5704x; 1.5704x over previous
#include <cuda_runtime.h>
#include <math.h>
#include <stdint.h>

// Problem dims
#define BATCH 32
#define EPS   1e-12f

// ---------------- packed global weight layout (per net, 44800 floats) -------
//  w1 : [tap(5)][o(64)][i(68 pad)]   21760   @ 0
//  w2 : [tap(5)][o(64)][i(68 pad)]   21760   @ 21760
//  w0 : [tap(4)][o(64)][i(4)]         1024   @ 43520
//  wo : [o(64)][ch(4)]                 256   @ 44544
#define NET_STRIDE 44800
#define WP_TOTAL   (2 * NET_STRIDE)

__device__ float g_wp[WP_TOTAL];

// ---------------- shared memory layout (floats) -----------------------------
#define SM_W1    0        // 21760
#define SM_W2    21760    // 21760
#define SM_W0    43520    // 1024
#define SM_WO    44544    // 256
#define SM_H0    44800    // 4096  [64px][64]
#define SM_H1    48896    // 4096
#define SM_RED1  52992    // 1024  [q 4][a 4][o 64]
#define SM_RED2  54016    // 1024
#define SM_Y     55040    // 256   [64px][4ch]
#define SM_X     55296    // 256
#define SM_LS    55552    // 256
#define SM_B0    55808    // 64
#define SM_B1    55872    // 64
#define SM_B2    55936    // 64
#define SM_BO    56000    // 4
#define SM_MLV   56004    // 32    [buf 2][a 4][ch 4]
#define SM_PART  56036    // 32    [a 4][half 2][ch 4]
#define SM_MBAR  56068    // 2     (8B aligned: 56068*4=224272)
#define SMEM_FLOATS 56072
#define SMEM_BYTES  (SMEM_FLOATS * 4)

// Mask-A taps (dr,dc): (-1,-1),(-1,0),(-1,1),(0,-1) ; Mask-B: A + center (0,0)
__global__ void repack_kernel(const float* __restrict__ mw0, const float* __restrict__ mw1,
                              const float* __restrict__ mw2, const float* __restrict__ mwo,
                              const float* __restrict__ lw0, const float* __restrict__ lw1,
                              const float* __restrict__ lw2, const float* __restrict__ lwo)
{
    int t = blockIdx.x * blockDim.x + threadIdx.x;
    if (t >= WP_TOTAL) return;
    const int krA[4] = {0,0,0,1}, kcA[4] = {0,1,2,0};
    const int krB[5] = {0,0,0,1,1}, kcB[5] = {0,1,2,0,1};
    int net = t / NET_STRIDE;
    int u   = t % NET_STRIDE;
    float v;
    if (u < 21760) {                       // w1: [tap][o][68]
        int tap = u / 4352, rem = u % 4352;
        int o = rem / 68, i = rem % 68;
        const float* w = net ? lw1 : mw1;
        v = (i < 64) ? w[((o * 64 + i) * 3 + krB[tap]) * 3 + kcB[tap]] : 0.f;
    } else if (u < 43520) {                // w2
        int u2 = u - 21760;
        int tap = u2 / 4352, rem = u2 % 4352;
        int o = rem / 68, i = rem % 68;
        const float* w = net ? lw2 : mw2;
        v = (i < 64) ? w[((o * 64 + i) * 3 + krB[tap]) * 3 + kcB[tap]] : 0.f;
    } else if (u < 44544) {                // w0: [tap][o][4]
        int u2 = u - 43520;
        int tap = u2 / 256, rem = u2 % 256;
        int o = rem / 4, i = rem % 4;
        const float* w = net ? lw0 : mw0;
        v = w[((o * 4 + i) * 3 + krA[tap]) * 3 + kcA[tap]];
    } else {                               // wo: [o][4]
        int u2 = u - 44544;
        int o = u2 / 4, ch = u2 % 4;
        const float* w = net ? lwo : mwo;
        v = w[ch * 64 + o];
    }
    g_wp[t] = v;
}

__device__ __forceinline__ float elu1(float v) {
    return v > 0.f ? v : (__expf(v) - 1.f);
}

__device__ __forceinline__ uint32_t smem_u32(const void* p) {
    uint32_t a;
    asm("{ .reg .u64 t; cvta.to.shared.u64 t, %1; cvt.u32.u64 %0, t; }" : "=r"(a) : "l"(p));
    return a;
}

__device__ __forceinline__ void st_remote_f32(uint32_t saddr, uint32_t rank, float v) {
    uint32_t raddr;
    asm volatile("mapa.shared::cluster.u32 %0, %1, %2;" : "=r"(raddr) : "r"(saddr), "r"(rank));
    asm volatile("st.shared::cluster.f32 [%0], %1;" :: "r"(raddr), "f"(v) : "memory");
}

__device__ __forceinline__ void arrive_remote(uint32_t mbar_saddr, uint32_t rank) {
    asm volatile(
        "{\n\t"
        ".reg .b32 r;\n\t"
        "mapa.shared::cluster.u32 r, %0, %1;\n\t"
        "mbarrier.arrive.release.cluster.shared::cluster.b64 _, [r];\n\t"
        "}"
        :: "r"(mbar_saddr), "r"(rank) : "memory");
}

__device__ __forceinline__ void mbar_wait(uint32_t mbar_saddr, uint32_t parity) {
    asm volatile(
        "{\n\t"
        ".reg .pred P1;\n\t"
        "WAIT_LOOP_%=:\n\t"
        "mbarrier.try_wait.parity.acquire.cluster.shared::cta.b64 P1, [%0], %1, 0x989680;\n\t"
        "@P1 bra.uni WAIT_DONE_%=;\n\t"
        "bra.uni WAIT_LOOP_%=;\n\t"
        "WAIT_DONE_%=:\n\t"
        "}"
        :: "r"(mbar_saddr), "r"(parity) : "memory");
}

__global__ void __cluster_dims__(2, 1, 1) __launch_bounds__(512, 1)
made_kernel(const float* __restrict__ x,
            const float* __restrict__ mb0, const float* __restrict__ mb1,
            const float* __restrict__ mb2, const float* __restrict__ mbo,
            const float* __restrict__ lb0, const float* __restrict__ lb1,
            const float* __restrict__ lb2, const float* __restrict__ lbo,
            float* __restrict__ out)
{
    extern __shared__ float sm[];
    const int tid = threadIdx.x;
    const int b = blockIdx.x >> 1;
    uint32_t net;
    asm("mov.u32 %0, %%cluster_ctarank;" : "=r"(net));
    const uint32_t peer = net ^ 1u;
    const uint32_t smbase = smem_u32(sm);
    const uint32_t mbar = smbase + SM_MBAR * 4u;

    // ---- startup: weights + state into smem ----
    {
        const float4* src = (const float4*)(g_wp + net * NET_STRIDE);
        float4* dst = (float4*)sm;
        #pragma unroll 4
        for (int i = tid; i < NET_STRIDE / 4; i += 512)
            dst[i] = src[i];
    }
    if (tid < 256) {
        int ch = tid >> 6, p = tid & 63;
        sm[SM_X + p * 4 + ch] = x[b * 256 + tid];
        sm[SM_Y + tid] = 0.f;
    }
    if (tid < 64) {
        sm[SM_B0 + tid] = net ? lb0[tid] : mb0[tid];
        sm[SM_B1 + tid] = net ? lb1[tid] : mb1[tid];
        sm[SM_B2 + tid] = net ? lb2[tid] : mb2[tid];
    }
    if (tid < 4) sm[SM_BO + tid] = net ? lbo[tid] : mbo[tid];
    if (tid == 0)
        asm volatile("mbarrier.init.shared.b64 [%0], %1;" :: "r"(mbar), "r"(16) : "memory");
    __syncthreads();
    asm volatile("barrier.cluster.arrive.aligned;" ::: "memory");
    asm volatile("barrier.cluster.wait.aligned;" ::: "memory");

    const int dRA[4] = {-1,-1,-1, 0}, dCA[4] = {-1, 0, 1,-1};
    const int dRB[4] = {-1,-1,-1, 0}, dCB[4] = {-1, 0, 1,-1};  // non-center B taps

    const int t8  = tid & 255;
    const int grp = tid >> 8;        // 0: L0 + G1nc, 1: G2nc
    const int o   = t8 & 63;
    const int q   = t8 >> 6;         // i-quarter (16 floats)

    for (int s = 0; s < 22; s++) {
        int rlo = (s - 6) > 0 ? (s - 6) / 2 : 0;
        int rhi = (s >> 1) < 7 ? (s >> 1) : 7;
        int npix = rhi - rlo + 1;

        int ra[4], ca[4], pa[4];
        #pragma unroll
        for (int a = 0; a < 4; a++) {
            ra[a] = rlo + a;
            ca[a] = s - 2 * ra[a];
            pa[a] = ra[a] * 8 + ca[a];
        }

        // ======== P1: L0 + non-center GEMM partials (all threads) ========
        if (grp == 0) {
            // ---- L0 (mask A, 4 -> 64): thread (o, a=q) ----
            if (q < npix) {
                float acc = sm[SM_B0 + o];
                #pragma unroll
                for (int tap = 0; tap < 4; tap++) {
                    int rr = ra[q] + dRA[tap], cc = ca[q] + dCA[tap];
                    if (rr >= 0 && cc >= 0 && cc < 8) {
                        float4 w = *(const float4*)(sm + SM_W0 + (tap * 64 + o) * 4);
                        float4 y4 = *(const float4*)(sm + SM_Y + (rr * 8 + cc) * 4);
                        acc += w.x * y4.x + w.y * y4.y + w.z * y4.z + w.w * y4.w;
                    }
                }
                sm[SM_H0 + pa[q] * 64 + o] = elu1(acc);
            }
            // ---- GEMM1 non-center partials over i-quarter q ----
            {
                float p0 = 0.f, p1 = 0.f, p2 = 0.f, p3 = 0.f;
                #pragma unroll
                for (int tap = 0; tap < 4; tap++) {
                    const float4* wr = (const float4*)(sm + SM_W1 + (tap * 64 + o) * 68 + q * 16);
                    float4 w0 = wr[0], w1 = wr[1], w2 = wr[2], w3 = wr[3];
                    #pragma unroll
                    for (int a = 0; a < 4; a++) {
                        int rr = ra[a] + dRB[tap], cc = ca[a] + dCB[tap];
                        if (a < npix && rr >= 0 && cc >= 0 && cc < 8) {
                            const float4* hp = (const float4*)(sm + SM_H0 + (rr * 8 + cc) * 64 + q * 16);
                            float4 h0 = hp[0], h1 = hp[1], h2 = hp[2], h3 = hp[3];
                            float v = w0.x*h0.x + w0.y*h0.y + w0.z*h0.z + w0.w*h0.w
                                    + w1.x*h1.x + w1.y*h1.y + w1.z*h1.z + w1.w*h1.w
                                    + w2.x*h2.x + w2.y*h2.y + w2.z*h2.z + w2.w*h2.w
                                    + w3.x*h3.x + w3.y*h3.y + w3.z*h3.z + w3.w*h3.w;
                            if (a == 0) p0 += v; else if (a == 1) p1 += v;
                            else if (a == 2) p2 += v; else p3 += v;
                        }
                    }
                }
                if (0 < npix) sm[SM_RED1 + (q * 4 + 0) * 64 + o] = p0;
                if (1 < npix) sm[SM_RED1 + (q * 4 + 1) * 64 + o] = p1;
                if (2 < npix) sm[SM_RED1 + (q * 4 + 2) * 64 + o] = p2;
                if (3 < npix) sm[SM_RED1 + (q * 4 + 3) * 64 + o] = p3;
            }
        } else {
            // ---- GEMM2 non-center partials (uses h1 from older diagonals) ----
            float p0 = 0.f, p1 = 0.f, p2 = 0.f, p3 = 0.f;
            #pragma unroll
            for (int tap = 0; tap < 4; tap++) {
                const float4* wr = (const float4*)(sm + SM_W2 + (tap * 64 + o) * 68 + q * 16);
                float4 w0 = wr[0], w1 = wr[1], w2 = wr[2], w3 = wr[3];
                #pragma unroll
                for (int a = 0; a < 4; a++) {
                    int rr = ra[a] + dRB[tap], cc = ca[a] + dCB[tap];
                    if (a < npix && rr >= 0 && cc >= 0 && cc < 8) {
                        const float4* hp = (const float4*)(sm + SM_H1 + (rr * 8 + cc) * 64 + q * 16);
                        float4 h0 = hp[0], h1 = hp[1], h2 = hp[2], h3 = hp[3];
                        float v = w0.x*h0.x + w0.y*h0.y + w0.z*h0.z + w0.w*h0.w
                                + w1.x*h1.x + w1.y*h1.y + w1.z*h1.z + w1.w*h1.w
                                + w2.x*h2.x + w2.y*h2.y + w2.z*h2.z + w2.w*h2.w
                                + w3.x*h3.x + w3.y*h3.y + w3.z*h3.z + w3.w*h3.w;
                        if (a == 0) p0 += v; else if (a == 1) p1 += v;
                        else if (a == 2) p2 += v; else p3 += v;
                    }
                }
            }
            if (0 < npix) sm[SM_RED2 + (q * 4 + 0) * 64 + o] = p0;
            if (1 < npix) sm[SM_RED2 + (q * 4 + 1) * 64 + o] = p1;
            if (2 < npix) sm[SM_RED2 + (q * 4 + 2) * 64 + o] = p2;
            if (3 < npix) sm[SM_RED2 + (q * 4 + 3) * 64 + o] = p3;
        }
        __syncthreads();

        // ======== P2: GEMM1 center tap + combine -> h1 (256 thr) ========
        if (tid < 256) {
            int o0 = tid & 63, a0 = tid >> 6;
            if (a0 < npix) {
                const float4* wr = (const float4*)(sm + SM_W1 + (4 * 64 + o0) * 68);
                const float4* hp = (const float4*)(sm + SM_H0 + pa[a0] * 64);
                float s0 = 0.f, s1 = 0.f, s2 = 0.f, s3 = 0.f;
                #pragma unroll
                for (int k = 0; k < 4; k++) {
                    float4 wA = wr[4*k+0], wB = wr[4*k+1], wC = wr[4*k+2], wD = wr[4*k+3];
                    float4 hA = hp[4*k+0], hB = hp[4*k+1], hC = hp[4*k+2], hD = hp[4*k+3];
                    s0 += wA.x*hA.x + wA.y*hA.y + wA.z*hA.z + wA.w*hA.w;
                    s1 += wB.x*hB.x + wB.y*hB.y + wB.z*hB.z + wB.w*hB.w;
                    s2 += wC.x*hC.x + wC.y*hC.y + wC.z*hC.z + wC.w*hC.w;
                    s3 += wD.x*hD.x + wD.y*hD.y + wD.z*hD.z + wD.w*hD.w;
                }
                float v = s0 + s1 + s2 + s3 + sm[SM_B1 + o0]
                        + sm[SM_RED1 + (0 * 4 + a0) * 64 + o0]
                        + sm[SM_RED1 + (1 * 4 + a0) * 64 + o0]
                        + sm[SM_RED1 + (2 * 4 + a0) * 64 + o0]
                        + sm[SM_RED1 + (3 * 4 + a0) * 64 + o0];
                sm[SM_H1 + pa[a0] * 64 + o0] = elu1(v);
            }
        }
        __syncthreads();

        // ======== P3: GEMM2 center tap + combine + out conv (256 thr) ========
        if (tid < 256) {
            int o0 = tid & 63, a0 = tid >> 6;
            int half = (tid >> 5) & 1;
            if (a0 < npix) {
                const float4* wr = (const float4*)(sm + SM_W2 + (4 * 64 + o0) * 68);
                const float4* hp = (const float4*)(sm + SM_H1 + pa[a0] * 64);
                float s0 = 0.f, s1 = 0.f, s2 = 0.f, s3 = 0.f;
                #pragma unroll
                for (int k = 0; k < 4; k++) {
                    float4 wA = wr[4*k+0], wB = wr[4*k+1], wC = wr[4*k+2], wD = wr[4*k+3];
                    float4 hA = hp[4*k+0], hB = hp[4*k+1], hC = hp[4*k+2], hD = hp[4*k+3];
                    s0 += wA.x*hA.x + wA.y*hA.y + wA.z*hA.z + wA.w*hA.w;
                    s1 += wB.x*hB.x + wB.y*hB.y + wB.z*hB.z + wB.w*hB.w;
                    s2 += wC.x*hC.x + wC.y*hC.y + wC.z*hC.z + wC.w*hC.w;
                    s3 += wD.x*hD.x + wD.y*hD.y + wD.z*hD.z + wD.w*hD.w;
                }
                float v = s0 + s1 + s2 + s3 + sm[SM_B2 + o0]
                        + sm[SM_RED2 + (0 * 4 + a0) * 64 + o0]
                        + sm[SM_RED2 + (1 * 4 + a0) * 64 + o0]
                        + sm[SM_RED2 + (2 * 4 + a0) * 64 + o0]
                        + sm[SM_RED2 + (3 * 4 + a0) * 64 + o0];
                v = elu1(v);
                float4 wo4 = *(const float4*)(sm + SM_WO + o0 * 4);
                float c0 = v * wo4.x, c1 = v * wo4.y, c2 = v * wo4.z, c3 = v * wo4.w;
                #pragma unroll
                for (int off = 16; off >= 1; off >>= 1) {
                    c0 += __shfl_down_sync(0xffffffffu, c0, off);
                    c1 += __shfl_down_sync(0xffffffffu, c1, off);
                    c2 += __shfl_down_sync(0xffffffffu, c2, off);
                    c3 += __shfl_down_sync(0xffffffffu, c3, off);
                }
                if ((tid & 31) == 0) {
                    float* pp = sm + SM_PART + (a0 * 2 + half) * 4;
                    pp[0] = c0; pp[1] = c1; pp[2] = c2; pp[3] = c3;
                }
            }
        }
        __syncthreads();

        // ======== P4: finalize + peer exchange + y update (16 thr) ========
        int buf = s & 1;
        if (tid < 16) {
            int a = tid >> 2, ch = tid & 3;
            float v = 0.f;
            if (a < npix) {
                v = sm[SM_PART + (a * 2 + 0) * 4 + ch]
                  + sm[SM_PART + (a * 2 + 1) * 4 + ch]
                  + sm[SM_BO + ch];
                uint32_t off = (uint32_t)(SM_MLV + buf * 16 + a * 4 + ch) * 4u;
                st_remote_f32(smbase + off, peer, v);
            }
            arrive_remote(mbar, peer);
            mbar_wait(mbar, (uint32_t)(s & 1));
            if (a < npix) {
                float pv = sm[SM_MLV + buf * 16 + a * 4 + ch];
                float mu = net ? pv : v;
                float ls = 0.5f * (net ? v : pv);
                int p = pa[a];
                float yv = (sm[SM_X + p * 4 + ch] - mu) / (__expf(ls) + EPS);
                sm[SM_Y + p * 4 + ch] = yv;
                sm[SM_LS + p * 4 + ch] = ls;
            }
        }
        __syncthreads();
    }

    // ---- outputs ----
    if (net == 0) {
        if (tid < 256)
            out[b * 256 + tid] = sm[SM_Y + (tid & 63) * 4 + (tid >> 6)];
    } else {
        if (tid < 32) {
            float a = 0.f;
            #pragma unroll
            for (int k = 0; k < 8; k++) a += sm[SM_LS + tid * 8 + k];
            #pragma unroll
            for (int off = 16; off >= 1; off >>= 1)
                a += __shfl_down_sync(0xffffffffu, a, off);
            if (tid == 0) out[BATCH * 256 + b] = a;
        }
    }

    asm volatile("barrier.cluster.arrive.aligned;" ::: "memory");
    asm volatile("barrier.cluster.wait.aligned;" ::: "memory");
}

extern "C" void kernel_launch(void* const* d_in, const int* in_sizes, int n_in,
                              void* d_out, int out_size)
{
    (void)in_sizes; (void)n_in; (void)out_size;
    const float* x   = (const float*)d_in[0];
    const float* mw0 = (const float*)d_in[1];
    const float* mb0 = (const float*)d_in[2];
    const float* mw1 = (const float*)d_in[3];
    const float* mb1 = (const float*)d_in[4];
    const float* mw2 = (const float*)d_in[5];
    const float* mb2 = (const float*)d_in[6];
    const float* mwo = (const float*)d_in[7];
    const float* mbo = (const float*)d_in[8];
    const float* lw0 = (const float*)d_in[9];
    const float* lb0 = (const float*)d_in[10];
    const float* lw1 = (const float*)d_in[11];
    const float* lb1 = (const float*)d_in[12];
    const float* lw2 = (const float*)d_in[13];
    const float* lb2 = (const float*)d_in[14];
    const float* lwo = (const float*)d_in[15];
    const float* lbo = (const float*)d_in[16];
    float* out = (float*)d_out;

    cudaFuncSetAttribute(made_kernel, cudaFuncAttributeMaxDynamicSharedMemorySize, SMEM_BYTES);

    repack_kernel<<<(WP_TOTAL + 255) / 256, 256>>>(mw0, mw1, mw2, mwo, lw0, lw1, lw2, lwo);
    made_kernel<<<2 * BATCH, 512, SMEM_BYTES>>>(x, mb0, mb1, mb2, mbo,
                                                lb0, lb1, lb2, lbo, out);
}